// round 14
// baseline (speedup 1.0000x reference)
#include <cuda_runtime.h>
#include <cuda_fp16.h>
#include <cstdint>

#define NNODES 2048
#define JDIM   768      // F_IN * T = 32*24
#define KCHEB  3
#define BATCH  16
#define FOUT   64
#define TDIM   24

// 302 MB scratch: rhs[b][m][k][f*24+t]
__device__ float g_rhs[(size_t)BATCH * NNODES * KCHEB * JDIM];
// 50 MB pre-packed x: half2{x[b][2np][j], x[b][2np+1][j]} at [b][np][j]
__device__ uint32_t g_xh[(size_t)BATCH * (NNODES / 2) * JDIM];

__device__ __forceinline__ uint32_t pack_h2(float lo, float hi) {
    __half2 h = __floats2half2_rn(lo, hi);
    return *reinterpret_cast<uint32_t*>(&h);
}
__device__ __forceinline__ uint32_t smem_u32(const void* p) {
    uint32_t a;
    asm("{ .reg .u64 t; cvta.to.shared.u64 t, %1; cvt.u32.u64 %0, t; }" : "=r"(a) : "l"(p));
    return a;
}
__device__ __forceinline__ void cp16(uint32_t dst, const void* src) {
    asm volatile("cp.async.ca.shared.global [%0], [%1], 16;" :: "r"(dst), "l"(src) : "memory");
}
__device__ __forceinline__ void mma_fp16(float d[4], const uint32_t a[4], const uint32_t b[2]) {
    asm("mma.sync.aligned.m16n8k16.row.col.f32.f16.f16.f32 "
        "{%0,%1,%2,%3}, {%4,%5,%6,%7}, {%8,%9}, {%0,%1,%2,%3};"
        : "+f"(d[0]), "+f"(d[1]), "+f"(d[2]), "+f"(d[3])
        : "r"(a[0]), "r"(a[1]), "r"(a[2]), "r"(a[3]),
          "r"(b[0]), "r"(b[1]));
}
// packed fp32x2 fma (Blackwell base ISA, PTX-only)
__device__ __forceinline__ void ffma2(uint64_t& d, uint64_t a, uint64_t b) {
    asm("fma.rn.f32x2 %0, %1, %2, %0;" : "+l"(d) : "l"(a), "l"(b));
}
__device__ __forceinline__ float2 u2f2(uint64_t u) {
    float2 f;
    asm("mov.b64 {%0,%1}, %2;" : "=f"(f.x), "=f"(f.y) : "l"(u));
    return f;
}

// ---------------------------------------------------------------------------
// Prepack: g_xh[b][np][j] = half2(x[b][2np][j], x[b][2np+1][j])
// ---------------------------------------------------------------------------
__global__ void __launch_bounds__(256)
prepack_kernel(const float* __restrict__ x)
{
    const int idx = blockIdx.x * 256 + threadIdx.x;
    const int b  = idx / (1024 * 192);
    const int r  = idx % (1024 * 192);
    const int np = r / 192;
    const int j4 = (r % 192) << 2;
    const size_t s0 = (size_t)(b * NNODES + (np << 1)) * JDIM + j4;
    const float4 a0 = *(const float4*)(x + s0);
    const float4 a1 = *(const float4*)(x + s0 + JDIM);
    uint4 o;
    o.x = pack_h2(a0.x, a1.x);  o.y = pack_h2(a0.y, a1.y);
    o.z = pack_h2(a0.z, a1.z);  o.w = pack_h2(a0.w, a1.w);
    *(uint4*)(g_xh + (size_t)(b * 1024 + np) * JDIM + j4) = o;
}

// ---------------------------------------------------------------------------
// Stage 1 (unchanged — 86% of the fp16 mma rt=16 issue floor)
// ---------------------------------------------------------------------------
__global__ void __launch_bounds__(256)
stage1_kernel(const float* __restrict__ att,
              const float* __restrict__ cheb)
{
    const int k  = blockIdx.z % KCHEB;
    const int b  = blockIdx.z / KCHEB;
    const int m0 = blockIdx.y << 7;
    const int j0 = blockIdx.x << 8;

    const float* __restrict__ Ac = cheb + (size_t)k * NNODES * NNODES;
    const float* __restrict__ Aa = att  + (size_t)b * NNODES * NNODES;

    __shared__ __align__(16) uint32_t As[2][16][136];
    __shared__ __align__(16) uint32_t Bs[2][16][264];

    const int tid  = threadIdx.x;
    const int lane = tid & 31;
    const int warp = tid >> 5;
    const int wm = (warp >> 2) << 6;
    const int wj = (warp & 3) << 6;
    const int g  = lane >> 2;
    const int ti = lane & 3;

    float acc[4][8][4];
#pragma unroll
    for (int i = 0; i < 4; ++i)
#pragma unroll
        for (int j = 0; j < 8; ++j)
#pragma unroll
            for (int c = 0; c < 4; ++c) acc[i][j][c] = 0.0f;

    float4 rc0[2], rc1[2], ra0[2], ra1[2];

    auto loadA = [&](int c) {
        const int n0 = c << 5;
#pragma unroll
        for (int i = 0; i < 2; ++i) {
            const int u  = tid + (i << 8);
            const int np = u >> 5;
            const int q  = u & 31;
            const size_t ro = (size_t)(n0 + (np << 1)) * NNODES + m0;
            rc0[i] = *((const float4*)(Ac + ro) + q);
            rc1[i] = *((const float4*)(Ac + ro + NNODES) + q);
            ra0[i] = *((const float4*)(Aa + ro) + q);
            ra1[i] = *((const float4*)(Aa + ro + NNODES) + q);
        }
    };
    auto storeA = [&](int nb) {
#pragma unroll
        for (int i = 0; i < 2; ++i) {
            const int u  = tid + (i << 8);
            const int np = u >> 5;
            const int q  = u & 31;
            uint4 ua;
            ua.x = pack_h2(rc0[i].x * ra0[i].x, rc1[i].x * ra1[i].x);
            ua.y = pack_h2(rc0[i].y * ra0[i].y, rc1[i].y * ra1[i].y);
            ua.z = pack_h2(rc0[i].z * ra0[i].z, rc1[i].z * ra1[i].z);
            ua.w = pack_h2(rc0[i].w * ra0[i].w, rc1[i].w * ra1[i].w);
            *(uint4*)&As[nb][np][q << 2] = ua;
        }
    };
    auto loadB = [&](int c, int nb) {
        const uint32_t base = smem_u32(&Bs[nb][0][0]);
        const uint32_t* src = g_xh + (size_t)(b * 1024 + (c << 4)) * JDIM + j0;
#pragma unroll
        for (int i = 0; i < 4; ++i) {
            const int l  = tid + (i << 8);
            const int np = l >> 6;
            const int o4 = (l & 63) << 2;
            cp16(base + (uint32_t)(np * 264 + o4) * 4, src + np * JDIM + o4);
        }
        asm volatile("cp.async.commit_group;" ::: "memory");
    };

    auto compute = [&](int buf) {
#pragma unroll
        for (int s = 0; s < 2; ++s) {
            const int r0 = (s << 3) + ti;
            const int r1 = r0 + 4;
            uint32_t af[4][4], bf[8][2];
#pragma unroll
            for (int i = 0; i < 4; ++i) {
                const int mi = wm + (i << 4);
                af[i][0] = As[buf][r0][mi + g];
                af[i][1] = As[buf][r0][mi + g + 8];
                af[i][2] = As[buf][r1][mi + g];
                af[i][3] = As[buf][r1][mi + g + 8];
            }
#pragma unroll
            for (int j = 0; j < 8; ++j) {
                const int nj = wj + (j << 3);
                bf[j][0] = Bs[buf][r0][nj + g];
                bf[j][1] = Bs[buf][r1][nj + g];
            }
#pragma unroll
            for (int i = 0; i < 4; ++i)
#pragma unroll
                for (int j = 0; j < 8; ++j)
                    mma_fp16(acc[i][j], af[i], bf[j]);
        }
    };

    loadA(0);
    loadB(0, 0);
    storeA(0);
    asm volatile("cp.async.wait_group 0;" ::: "memory");
    __syncthreads();

    for (int c = 0; c < 64; ++c) {
        const int buf = c & 1, nb = buf ^ 1;
        if (c < 63) {
            loadB(c + 1, nb);
            loadA(c + 1);
        }
        compute(buf);
        if (c < 63) {
            storeA(nb);
            asm volatile("cp.async.wait_group 0;" ::: "memory");
        }
        __syncthreads();
    }

#pragma unroll
    for (int i = 0; i < 4; ++i) {
#pragma unroll
        for (int h = 0; h < 2; ++h) {
            const int row = m0 + wm + (i << 4) + g + (h << 3);
            float* orow = g_rhs
                        + (((size_t)b * NNODES + row) * KCHEB + k) * JDIM
                        + j0 + wj + (ti << 1);
#pragma unroll
            for (int j = 0; j < 8; ++j) {
                float2 v = make_float2(acc[i][j][h << 1], acc[i][j][(h << 1) + 1]);
                *(float2*)(orow + (j << 3)) = v;
            }
        }
    }
}

// ---------------------------------------------------------------------------
// Stage 2 v4: out[b,m,o,t] = relu( sum_{kf} rhs[b,m,kf,t] * Theta[kf,o] )
// 128 threads, 2 rows/CTA (16384 CTAs, 3 CTAs/SM). Thread tile 4o x 6t with
// f32x2 accumulators paired over (t,t+1). Theta duplicated (w,w) as u64 in a
// 68-per-64 padded layout: slot = kf*68 + o + (o>>4) -> the 16 distinct warp
// addresses hit 16 distinct even banks (conflict-free LDS.64, no reg dup).
// Per warp per kf: 7 conflict-free LDS.64 + 12 FFMA2.
// ---------------------------------------------------------------------------
#define S2_WBYTES  (96 * 68 * 8)                        // 52224
#define S2_SMEM    (S2_WBYTES + 2 * KCHEB * JDIM * 4)   // 70656

__global__ void __launch_bounds__(128)
stage2_kernel(const float* __restrict__ Theta, float* __restrict__ out)
{
    extern __shared__ __align__(16) char s2[];
    uint64_t* sW = (uint64_t*)s2;                 // [96][68] dup'd padded Theta
    float*    sR = (float*)(s2 + S2_WBYTES);      // [2][2304]

    const int tid = threadIdx.x;

    // fill Theta: 12 x float4, each scatters 4 dup'd u64 slots (same 16-block)
#pragma unroll
    for (int i = 0; i < 12; ++i) {
        const int l  = (tid + (i << 7)) << 2;     // 0..6140, multiple of 4
        const int kf = l >> 6, o = l & 63;
        const float4 v = *(const float4*)(Theta + l);
        uint64_t* dst = sW + kf * 68 + o + (o >> 4);
        const uint32_t ux = __float_as_uint(v.x), uy = __float_as_uint(v.y);
        const uint32_t uz = __float_as_uint(v.z), uw = __float_as_uint(v.w);
        dst[0] = ((uint64_t)ux << 32) | ux;
        dst[1] = ((uint64_t)uy << 32) | uy;
        dst[2] = ((uint64_t)uz << 32) | uz;
        dst[3] = ((uint64_t)uw << 32) | uw;
    }
    const size_t bm0 = (size_t)blockIdx.x << 1;
    const float4* rsrc = (const float4*)(g_rhs + bm0 * (KCHEB * JDIM));
    float4* rdst = (float4*)sR;
#pragma unroll
    for (int i = 0; i < 9; ++i) {
        const int l = tid + (i << 7);             // 0..1151
        rdst[l] = rsrc[l];
    }
    __syncthreads();

    const int sub = tid >> 6;
    const int t64 = tid & 63;
    const int o0  = (t64 & 15) << 2;     // 4 consecutive o
    const int tb  = (t64 >> 4) * 6;      // 6 consecutive t (3 pairs)
    const float* R = sR + sub * (KCHEB * JDIM);
    const int wbase = o0 + (o0 >> 4);    // padded slot offset for o0

    uint64_t acc[4][3];
#pragma unroll
    for (int i = 0; i < 4; ++i)
#pragma unroll
        for (int j = 0; j < 3; ++j) acc[i][j] = 0ull;

#pragma unroll 4
    for (int kf = 0; kf < 96; ++kf) {
        const uint64_t* wp = sW + kf * 68 + wbase;
        const uint64_t w0 = wp[0], w1 = wp[1], w2 = wp[2], w3 = wp[3];
        const uint64_t* rp = (const uint64_t*)(R + kf * TDIM + tb);
        const uint64_t r0 = rp[0], r1 = rp[1], r2 = rp[2];

        ffma2(acc[0][0], w0, r0); ffma2(acc[0][1], w0, r1); ffma2(acc[0][2], w0, r2);
        ffma2(acc[1][0], w1, r0); ffma2(acc[1][1], w1, r1); ffma2(acc[1][2], w1, r2);
        ffma2(acc[2][0], w2, r0); ffma2(acc[2][1], w2, r1); ffma2(acc[2][2], w2, r2);
        ffma2(acc[3][0], w3, r0); ffma2(acc[3][1], w3, r1); ffma2(acc[3][2], w3, r2);
    }

    float* obase = out + (bm0 + sub) * (FOUT * TDIM);
#pragma unroll
    for (int i = 0; i < 4; ++i) {
        float* orow = obase + (o0 + i) * TDIM + tb;
#pragma unroll
        for (int j = 0; j < 3; ++j) {
            float2 v = u2f2(acc[i][j]);
            v.x = fmaxf(v.x, 0.0f);
            v.y = fmaxf(v.y, 0.0f);
            *(float2*)(orow + (j << 1)) = v;
        }
    }
}

// ---------------------------------------------------------------------------
extern "C" void kernel_launch(void* const* d_in, const int* in_sizes, int n_in,
                              void* d_out, int out_size)
{
    (void)in_sizes; (void)n_in; (void)out_size;
    const float* x     = (const float*)d_in[0];   // (16,2048,32,24)
    const float* att   = (const float*)d_in[1];   // (16,2048,2048)
    const float* cheb  = (const float*)d_in[2];   // (3,2048,2048)
    const float* Theta = (const float*)d_in[3];   // (3,32,64)
    float* out = (float*)d_out;                   // (16,2048,64,24)

    cudaFuncSetAttribute(stage2_kernel,
                         cudaFuncAttributeMaxDynamicSharedMemorySize, S2_SMEM);

    prepack_kernel<<<BATCH * 1024 * 192 / 256, 256>>>(x);
    dim3 g1(JDIM / 256, NNODES / 128, KCHEB * BATCH);   // (3, 16, 48)
    stage1_kernel<<<g1, 256>>>(att, cheb);
    stage2_kernel<<<(BATCH * NNODES) / 2, 128, S2_SMEM>>>(Theta, out);
}

// round 15
// speedup vs baseline: 1.1654x; 1.1654x over previous
#include <cuda_runtime.h>
#include <cuda_fp16.h>
#include <cstdint>

#define NNODES 2048
#define JDIM   768      // F_IN * T = 32*24
#define KCHEB  3
#define BATCH  16
#define FOUT   64
#define TDIM   24
#define KF     96       // KCHEB * F_IN

// 302 MB scratch: rhs[b][m][kf][t]
__device__ float g_rhs[(size_t)BATCH * NNODES * KCHEB * JDIM];
// 50 MB pre-packed x: half2{x[b][2np][j], x[b][2np+1][j]} at [b][np][j]
__device__ uint32_t g_xh[(size_t)BATCH * (NNODES / 2) * JDIM];
// 24 KB Theta as tf32, layout [kf][o]
__device__ uint32_t g_tht[KF * FOUT];

__device__ __forceinline__ uint32_t pack_h2(float lo, float hi) {
    __half2 h = __floats2half2_rn(lo, hi);
    return *reinterpret_cast<uint32_t*>(&h);
}
__device__ __forceinline__ uint32_t f2tf(float f) {
    uint32_t u; asm("cvt.rna.tf32.f32 %0, %1;" : "=r"(u) : "f"(f)); return u;
}
__device__ __forceinline__ uint32_t smem_u32(const void* p) {
    uint32_t a;
    asm("{ .reg .u64 t; cvta.to.shared.u64 t, %1; cvt.u32.u64 %0, t; }" : "=r"(a) : "l"(p));
    return a;
}
__device__ __forceinline__ void cp16(uint32_t dst, const void* src) {
    asm volatile("cp.async.ca.shared.global [%0], [%1], 16;" :: "r"(dst), "l"(src) : "memory");
}
__device__ __forceinline__ void mma_fp16(float d[4], const uint32_t a[4], const uint32_t b[2]) {
    asm("mma.sync.aligned.m16n8k16.row.col.f32.f16.f16.f32 "
        "{%0,%1,%2,%3}, {%4,%5,%6,%7}, {%8,%9}, {%0,%1,%2,%3};"
        : "+f"(d[0]), "+f"(d[1]), "+f"(d[2]), "+f"(d[3])
        : "r"(a[0]), "r"(a[1]), "r"(a[2]), "r"(a[3]),
          "r"(b[0]), "r"(b[1]));
}
__device__ __forceinline__ void mma_tf32(float d[4], const uint32_t a[4], const uint32_t b[2]) {
    asm("mma.sync.aligned.m16n8k8.row.col.f32.tf32.tf32.f32 "
        "{%0,%1,%2,%3}, {%4,%5,%6,%7}, {%8,%9}, {%0,%1,%2,%3};"
        : "+f"(d[0]), "+f"(d[1]), "+f"(d[2]), "+f"(d[3])
        : "r"(a[0]), "r"(a[1]), "r"(a[2]), "r"(a[3]),
          "r"(b[0]), "r"(b[1]));
}

// ---------------------------------------------------------------------------
// Prepack x: g_xh[b][np][j] = half2(x[b][2np][j], x[b][2np+1][j])
// ---------------------------------------------------------------------------
__global__ void __launch_bounds__(256)
prepack_kernel(const float* __restrict__ x)
{
    const int idx = blockIdx.x * 256 + threadIdx.x;
    const int b  = idx / (1024 * 192);
    const int r  = idx % (1024 * 192);
    const int np = r / 192;
    const int j4 = (r % 192) << 2;
    const size_t s0 = (size_t)(b * NNODES + (np << 1)) * JDIM + j4;
    const float4 a0 = *(const float4*)(x + s0);
    const float4 a1 = *(const float4*)(x + s0 + JDIM);
    uint4 o;
    o.x = pack_h2(a0.x, a1.x);  o.y = pack_h2(a0.y, a1.y);
    o.z = pack_h2(a0.z, a1.z);  o.w = pack_h2(a0.w, a1.w);
    *(uint4*)(g_xh + (size_t)(b * 1024 + np) * JDIM + j4) = o;
}

// Prepack Theta to tf32 (layout already [kf][o])
__global__ void __launch_bounds__(256)
theta_prepack_kernel(const float* __restrict__ Theta)
{
    const int i = blockIdx.x * 256 + threadIdx.x;   // 0..6143
    g_tht[i] = f2tf(Theta[i]);
}

// ---------------------------------------------------------------------------
// Stage 1 (unchanged — 93% of the fp16 mma issue floor)
// ---------------------------------------------------------------------------
__global__ void __launch_bounds__(256)
stage1_kernel(const float* __restrict__ att,
              const float* __restrict__ cheb)
{
    const int k  = blockIdx.z % KCHEB;
    const int b  = blockIdx.z / KCHEB;
    const int m0 = blockIdx.y << 7;
    const int j0 = blockIdx.x << 8;

    const float* __restrict__ Ac = cheb + (size_t)k * NNODES * NNODES;
    const float* __restrict__ Aa = att  + (size_t)b * NNODES * NNODES;

    __shared__ __align__(16) uint32_t As[2][16][136];
    __shared__ __align__(16) uint32_t Bs[2][16][264];

    const int tid  = threadIdx.x;
    const int lane = tid & 31;
    const int warp = tid >> 5;
    const int wm = (warp >> 2) << 6;
    const int wj = (warp & 3) << 6;
    const int g  = lane >> 2;
    const int ti = lane & 3;

    float acc[4][8][4];
#pragma unroll
    for (int i = 0; i < 4; ++i)
#pragma unroll
        for (int j = 0; j < 8; ++j)
#pragma unroll
            for (int c = 0; c < 4; ++c) acc[i][j][c] = 0.0f;

    float4 rc0[2], rc1[2], ra0[2], ra1[2];

    auto loadA = [&](int c) {
        const int n0 = c << 5;
#pragma unroll
        for (int i = 0; i < 2; ++i) {
            const int u  = tid + (i << 8);
            const int np = u >> 5;
            const int q  = u & 31;
            const size_t ro = (size_t)(n0 + (np << 1)) * NNODES + m0;
            rc0[i] = *((const float4*)(Ac + ro) + q);
            rc1[i] = *((const float4*)(Ac + ro + NNODES) + q);
            ra0[i] = *((const float4*)(Aa + ro) + q);
            ra1[i] = *((const float4*)(Aa + ro + NNODES) + q);
        }
    };
    auto storeA = [&](int nb) {
#pragma unroll
        for (int i = 0; i < 2; ++i) {
            const int u  = tid + (i << 8);
            const int np = u >> 5;
            const int q  = u & 31;
            uint4 ua;
            ua.x = pack_h2(rc0[i].x * ra0[i].x, rc1[i].x * ra1[i].x);
            ua.y = pack_h2(rc0[i].y * ra0[i].y, rc1[i].y * ra1[i].y);
            ua.z = pack_h2(rc0[i].z * ra0[i].z, rc1[i].z * ra1[i].z);
            ua.w = pack_h2(rc0[i].w * ra0[i].w, rc1[i].w * ra1[i].w);
            *(uint4*)&As[nb][np][q << 2] = ua;
        }
    };
    auto loadB = [&](int c, int nb) {
        const uint32_t base = smem_u32(&Bs[nb][0][0]);
        const uint32_t* src = g_xh + (size_t)(b * 1024 + (c << 4)) * JDIM + j0;
#pragma unroll
        for (int i = 0; i < 4; ++i) {
            const int l  = tid + (i << 8);
            const int np = l >> 6;
            const int o4 = (l & 63) << 2;
            cp16(base + (uint32_t)(np * 264 + o4) * 4, src + np * JDIM + o4);
        }
        asm volatile("cp.async.commit_group;" ::: "memory");
    };

    auto compute = [&](int buf) {
#pragma unroll
        for (int s = 0; s < 2; ++s) {
            const int r0 = (s << 3) + ti;
            const int r1 = r0 + 4;
            uint32_t af[4][4], bf[8][2];
#pragma unroll
            for (int i = 0; i < 4; ++i) {
                const int mi = wm + (i << 4);
                af[i][0] = As[buf][r0][mi + g];
                af[i][1] = As[buf][r0][mi + g + 8];
                af[i][2] = As[buf][r1][mi + g];
                af[i][3] = As[buf][r1][mi + g + 8];
            }
#pragma unroll
            for (int j = 0; j < 8; ++j) {
                const int nj = wj + (j << 3);
                bf[j][0] = Bs[buf][r0][nj + g];
                bf[j][1] = Bs[buf][r1][nj + g];
            }
#pragma unroll
            for (int i = 0; i < 4; ++i)
#pragma unroll
                for (int j = 0; j < 8; ++j)
                    mma_fp16(acc[i][j], af[i], bf[j]);
        }
    };

    loadA(0);
    loadB(0, 0);
    storeA(0);
    asm volatile("cp.async.wait_group 0;" ::: "memory");
    __syncthreads();

    for (int c = 0; c < 64; ++c) {
        const int buf = c & 1, nb = buf ^ 1;
        if (c < 63) {
            loadB(c + 1, nb);
            loadA(c + 1);
        }
        compute(buf);
        if (c < 63) {
            storeA(nb);
            asm volatile("cp.async.wait_group 0;" ::: "memory");
        }
        __syncthreads();
    }

#pragma unroll
    for (int i = 0; i < 4; ++i) {
#pragma unroll
        for (int h = 0; h < 2; ++h) {
            const int row = m0 + wm + (i << 4) + g + (h << 3);
            float* orow = g_rhs
                        + (((size_t)b * NNODES + row) * KCHEB + k) * JDIM
                        + j0 + wj + (ti << 1);
#pragma unroll
            for (int j = 0; j < 8; ++j) {
                float2 v = make_float2(acc[i][j][h << 1], acc[i][j][(h << 1) + 1]);
                *(float2*)(orow + (j << 3)) = v;
            }
        }
    }
}

// ---------------------------------------------------------------------------
// Stage 2 v6 (tensor cores): per row, out(64o x 24t) = Theta^T(64x96) * rhs(96x24)
// tf32 m16n8k8: o = 4 m-tiles, t = 3 n-tiles, kf = 12 k-steps.
// 128 threads = 4 warps, one row per warp, 4 rows/CTA (8192 CTAs, 5 CTAs/SM).
// B staged transposed in smem sRt[t][kf] pitch 100 (banks 4g+ti: conflict-free).
// A loaded straight from L1-resident g_tht (tf32) per fragment.
// Fragment mappings identical to the verified round-5 tf32 stage1.
// ---------------------------------------------------------------------------
#define S2_ROWS 4
#define S2_PITCH 100

__global__ void __launch_bounds__(128)
stage2_kernel(float* __restrict__ out)
{
    __shared__ uint32_t sRt[S2_ROWS][TDIM * S2_PITCH];   // 38400 B, tf32

    const int tid = threadIdx.x;
    const size_t row0 = (size_t)blockIdx.x * S2_ROWS;

    // fill: transpose rhs[r][kf][t] -> sRt[r][t*100+kf], cvt to tf32
#pragma unroll
    for (int jj = 0; jj < 3; ++jj) {
        const int rk = tid + (jj << 7);          // 0..383 over 4*96 kf-rows
        const int r4 = rk / KF, kf = rk % KF;
        const float* src = g_rhs + (row0 + r4) * (KF * TDIM) + kf * TDIM;
        float4 v[6];
#pragma unroll
        for (int q = 0; q < 6; ++q) v[q] = *(const float4*)(src + (q << 2));
        uint32_t* dst = &sRt[r4][kf];
#pragma unroll
        for (int q = 0; q < 6; ++q) {
            dst[((q << 2) + 0) * S2_PITCH] = f2tf(v[q].x);
            dst[((q << 2) + 1) * S2_PITCH] = f2tf(v[q].y);
            dst[((q << 2) + 2) * S2_PITCH] = f2tf(v[q].z);
            dst[((q << 2) + 3) * S2_PITCH] = f2tf(v[q].w);
        }
    }
    __syncthreads();

    const int w    = tid >> 5;
    const int lane = tid & 31;
    const int g    = lane >> 2;
    const int ti   = lane & 3;

    float acc[4][3][4];
#pragma unroll
    for (int mi = 0; mi < 4; ++mi)
#pragma unroll
        for (int nt = 0; nt < 3; ++nt)
#pragma unroll
            for (int c = 0; c < 4; ++c) acc[mi][nt][c] = 0.0f;

#pragma unroll
    for (int ks = 0; ks < 12; ++ks) {
        const int k0 = (ks << 3) + ti;
        const int k1 = k0 + 4;
        uint32_t af[4][4], bf[3][2];
#pragma unroll
        for (int mi = 0; mi < 4; ++mi) {
            const int o = (mi << 4) + g;
            af[mi][0] = g_tht[k0 * FOUT + o];
            af[mi][1] = g_tht[k0 * FOUT + o + 8];
            af[mi][2] = g_tht[k1 * FOUT + o];
            af[mi][3] = g_tht[k1 * FOUT + o + 8];
        }
#pragma unroll
        for (int nt = 0; nt < 3; ++nt) {
            const int t = (nt << 3) + g;
            bf[nt][0] = sRt[w][t * S2_PITCH + k0];
            bf[nt][1] = sRt[w][t * S2_PITCH + k1];
        }
#pragma unroll
        for (int mi = 0; mi < 4; ++mi)
#pragma unroll
            for (int nt = 0; nt < 3; ++nt)
                mma_tf32(acc[mi][nt], af[mi], bf[nt]);
    }

    // epilogue: c0:(g,2ti) c1:(g,2ti+1) c2:(g+8,2ti) c3:(g+8,2ti+1)
    float* ob = out + (row0 + w) * (FOUT * TDIM);
#pragma unroll
    for (int mi = 0; mi < 4; ++mi) {
        const int o = (mi << 4) + g;
#pragma unroll
        for (int nt = 0; nt < 3; ++nt) {
            const int t = (nt << 3) + (ti << 1);
            float2 v0 = make_float2(fmaxf(acc[mi][nt][0], 0.0f),
                                    fmaxf(acc[mi][nt][1], 0.0f));
            float2 v1 = make_float2(fmaxf(acc[mi][nt][2], 0.0f),
                                    fmaxf(acc[mi][nt][3], 0.0f));
            *(float2*)(ob + o * TDIM + t) = v0;
            *(float2*)(ob + (o + 8) * TDIM + t) = v1;
        }
    }
}

// ---------------------------------------------------------------------------
extern "C" void kernel_launch(void* const* d_in, const int* in_sizes, int n_in,
                              void* d_out, int out_size)
{
    (void)in_sizes; (void)n_in; (void)out_size;
    const float* x     = (const float*)d_in[0];   // (16,2048,32,24)
    const float* att   = (const float*)d_in[1];   // (16,2048,2048)
    const float* cheb  = (const float*)d_in[2];   // (3,2048,2048)
    const float* Theta = (const float*)d_in[3];   // (3,32,64)
    float* out = (float*)d_out;                   // (16,2048,64,24)

    prepack_kernel<<<BATCH * 1024 * 192 / 256, 256>>>(x);
    theta_prepack_kernel<<<KF * FOUT / 256, 256>>>(Theta);
    dim3 g1(JDIM / 256, NNODES / 128, KCHEB * BATCH);   // (3, 16, 48)
    stage1_kernel<<<g1, 256>>>(att, cheb);
    stage2_kernel<<<(BATCH * NNODES) / S2_ROWS, 128>>>(out);
}

// round 16
// speedup vs baseline: 1.2257x; 1.0518x over previous
#include <cuda_runtime.h>
#include <cuda_fp16.h>
#include <cstdint>

#define NNODES 2048
#define JDIM   768      // F_IN * T = 32*24
#define KCHEB  3
#define BATCH  16
#define FOUT   64
#define TDIM   24
#define KF     96       // KCHEB * F_IN

// 151 MB fp16 scratch: half2{rhs[b][m][kf][t], rhs[..][t+1]} at [b*2048+m][kf][t/2]
__device__ uint32_t g_rhsh[(size_t)BATCH * NNODES * KF * (TDIM / 2)];
// 50 MB pre-packed x: half2{x[b][2np][j], x[b][2np+1][j]} at [b][np][j]
__device__ uint32_t g_xh[(size_t)BATCH * (NNODES / 2) * JDIM];
// 12 KB Theta as half2 pairs over kf: g_thh[kp][o] = h2(Theta[2kp][o], Theta[2kp+1][o])
__device__ uint32_t g_thh[(KF / 2) * FOUT];

__device__ __forceinline__ uint32_t pack_h2(float lo, float hi) {
    __half2 h = __floats2half2_rn(lo, hi);
    return *reinterpret_cast<uint32_t*>(&h);
}
__device__ __forceinline__ uint32_t smem_u32(const void* p) {
    uint32_t a;
    asm("{ .reg .u64 t; cvta.to.shared.u64 t, %1; cvt.u32.u64 %0, t; }" : "=r"(a) : "l"(p));
    return a;
}
__device__ __forceinline__ void cp16(uint32_t dst, const void* src) {
    asm volatile("cp.async.ca.shared.global [%0], [%1], 16;" :: "r"(dst), "l"(src) : "memory");
}
__device__ __forceinline__ void mma_fp16(float d[4], const uint32_t a[4], const uint32_t b[2]) {
    asm("mma.sync.aligned.m16n8k16.row.col.f32.f16.f16.f32 "
        "{%0,%1,%2,%3}, {%4,%5,%6,%7}, {%8,%9}, {%0,%1,%2,%3};"
        : "+f"(d[0]), "+f"(d[1]), "+f"(d[2]), "+f"(d[3])
        : "r"(a[0]), "r"(a[1]), "r"(a[2]), "r"(a[3]),
          "r"(b[0]), "r"(b[1]));
}

// ---------------------------------------------------------------------------
// Prepack x: g_xh[b][np][j] = half2(x[b][2np][j], x[b][2np+1][j])
// ---------------------------------------------------------------------------
__global__ void __launch_bounds__(256)
prepack_kernel(const float* __restrict__ x)
{
    const int idx = blockIdx.x * 256 + threadIdx.x;
    const int b  = idx / (1024 * 192);
    const int r  = idx % (1024 * 192);
    const int np = r / 192;
    const int j4 = (r % 192) << 2;
    const size_t s0 = (size_t)(b * NNODES + (np << 1)) * JDIM + j4;
    const float4 a0 = *(const float4*)(x + s0);
    const float4 a1 = *(const float4*)(x + s0 + JDIM);
    uint4 o;
    o.x = pack_h2(a0.x, a1.x);  o.y = pack_h2(a0.y, a1.y);
    o.z = pack_h2(a0.z, a1.z);  o.w = pack_h2(a0.w, a1.w);
    *(uint4*)(g_xh + (size_t)(b * 1024 + np) * JDIM + j4) = o;
}

// Prepack Theta: pairs over adjacent kf rows
__global__ void __launch_bounds__(256)
theta_prepack_kernel(const float* __restrict__ Theta)
{
    const int i  = blockIdx.x * 256 + threadIdx.x;   // 0..3071
    const int kp = i >> 6, o = i & 63;
    g_thh[i] = pack_h2(Theta[(kp << 1) * FOUT + o],
                       Theta[((kp << 1) + 1) * FOUT + o]);
}

// ---------------------------------------------------------------------------
// Stage 1: rhs[m,j] = sum_n (cheb[k][n][m]*att[b][n][m]) * x[b][n][j]
// fp16 m16n8k16, CTA 128m x 256j, K-chunk 32n, 256 threads, 8 warps 2x4.
// Epilogue now writes fp16 half2 (t,t+1) pairs into g_rhsh [row][kf][t/2].
// ---------------------------------------------------------------------------
__global__ void __launch_bounds__(256)
stage1_kernel(const float* __restrict__ att,
              const float* __restrict__ cheb)
{
    const int k  = blockIdx.z % KCHEB;
    const int b  = blockIdx.z / KCHEB;
    const int m0 = blockIdx.y << 7;
    const int j0 = blockIdx.x << 8;

    const float* __restrict__ Ac = cheb + (size_t)k * NNODES * NNODES;
    const float* __restrict__ Aa = att  + (size_t)b * NNODES * NNODES;

    __shared__ __align__(16) uint32_t As[2][16][136];
    __shared__ __align__(16) uint32_t Bs[2][16][264];

    const int tid  = threadIdx.x;
    const int lane = tid & 31;
    const int warp = tid >> 5;
    const int wm = (warp >> 2) << 6;
    const int wj = (warp & 3) << 6;
    const int g  = lane >> 2;
    const int ti = lane & 3;

    float acc[4][8][4];
#pragma unroll
    for (int i = 0; i < 4; ++i)
#pragma unroll
        for (int j = 0; j < 8; ++j)
#pragma unroll
            for (int c = 0; c < 4; ++c) acc[i][j][c] = 0.0f;

    float4 rc0[2], rc1[2], ra0[2], ra1[2];

    auto loadA = [&](int c) {
        const int n0 = c << 5;
#pragma unroll
        for (int i = 0; i < 2; ++i) {
            const int u  = tid + (i << 8);
            const int np = u >> 5;
            const int q  = u & 31;
            const size_t ro = (size_t)(n0 + (np << 1)) * NNODES + m0;
            rc0[i] = *((const float4*)(Ac + ro) + q);
            rc1[i] = *((const float4*)(Ac + ro + NNODES) + q);
            ra0[i] = *((const float4*)(Aa + ro) + q);
            ra1[i] = *((const float4*)(Aa + ro + NNODES) + q);
        }
    };
    auto storeA = [&](int nb) {
#pragma unroll
        for (int i = 0; i < 2; ++i) {
            const int u  = tid + (i << 8);
            const int np = u >> 5;
            const int q  = u & 31;
            uint4 ua;
            ua.x = pack_h2(rc0[i].x * ra0[i].x, rc1[i].x * ra1[i].x);
            ua.y = pack_h2(rc0[i].y * ra0[i].y, rc1[i].y * ra1[i].y);
            ua.z = pack_h2(rc0[i].z * ra0[i].z, rc1[i].z * ra1[i].z);
            ua.w = pack_h2(rc0[i].w * ra0[i].w, rc1[i].w * ra1[i].w);
            *(uint4*)&As[nb][np][q << 2] = ua;
        }
    };
    auto loadB = [&](int c, int nb) {
        const uint32_t base = smem_u32(&Bs[nb][0][0]);
        const uint32_t* src = g_xh + (size_t)(b * 1024 + (c << 4)) * JDIM + j0;
#pragma unroll
        for (int i = 0; i < 4; ++i) {
            const int l  = tid + (i << 8);
            const int np = l >> 6;
            const int o4 = (l & 63) << 2;
            cp16(base + (uint32_t)(np * 264 + o4) * 4, src + np * JDIM + o4);
        }
        asm volatile("cp.async.commit_group;" ::: "memory");
    };

    auto compute = [&](int buf) {
#pragma unroll
        for (int s = 0; s < 2; ++s) {
            const int r0 = (s << 3) + ti;
            const int r1 = r0 + 4;
            uint32_t af[4][4], bf[8][2];
#pragma unroll
            for (int i = 0; i < 4; ++i) {
                const int mi = wm + (i << 4);
                af[i][0] = As[buf][r0][mi + g];
                af[i][1] = As[buf][r0][mi + g + 8];
                af[i][2] = As[buf][r1][mi + g];
                af[i][3] = As[buf][r1][mi + g + 8];
            }
#pragma unroll
            for (int j = 0; j < 8; ++j) {
                const int nj = wj + (j << 3);
                bf[j][0] = Bs[buf][r0][nj + g];
                bf[j][1] = Bs[buf][r1][nj + g];
            }
#pragma unroll
            for (int i = 0; i < 4; ++i)
#pragma unroll
                for (int j = 0; j < 8; ++j)
                    mma_fp16(acc[i][j], af[i], bf[j]);
        }
    };

    loadA(0);
    loadB(0, 0);
    storeA(0);
    asm volatile("cp.async.wait_group 0;" ::: "memory");
    __syncthreads();

    for (int c = 0; c < 64; ++c) {
        const int buf = c & 1, nb = buf ^ 1;
        if (c < 63) {
            loadB(c + 1, nb);
            loadA(c + 1);
        }
        compute(buf);
        if (c < 63) {
            storeA(nb);
            asm volatile("cp.async.wait_group 0;" ::: "memory");
        }
        __syncthreads();
    }

    // Epilogue: pairs (jj, jj+1) = (t, t+1), t even; write half2 to g_rhsh
    const int jb = j0 + wj + (ti << 1);
#pragma unroll
    for (int i = 0; i < 4; ++i) {
#pragma unroll
        for (int h = 0; h < 2; ++h) {
            const int row = m0 + wm + (i << 4) + g + (h << 3);
            uint32_t* obase = g_rhsh
                            + ((size_t)(b * NNODES) + row) * (KF * 12)
                            + k * 32 * 12;
#pragma unroll
            for (int j = 0; j < 8; ++j) {
                const int jj = jb + (j << 3);
                const int f  = jj / 24;
                const int t  = jj - f * 24;
                obase[f * 12 + (t >> 1)] =
                    pack_h2(acc[i][j][h << 1], acc[i][j][(h << 1) + 1]);
            }
        }
    }
}

// ---------------------------------------------------------------------------
// Stage 2 v7 (fp16 tensor, zero smem): per row,
//   out(64o x 24t) = Theta^T(64 x 96kf) * rhs(96kf x 24t)
// fp16 m16n8k16: o = 4 m-tiles, t = 3 n-tiles, kf = 6 k-steps of 16.
// 128 threads = 4 warps, one row per warp, 4 rows/CTA, grid 8192. No smem,
// no __syncthreads. A frags from L1-resident g_thh; B frags merged in regs
// from g_rhsh via byte_perm (parity of g picks t-even/odd halves).
// Fragment mappings identical to the verified stage1 fp16 path.
// ---------------------------------------------------------------------------
__global__ void __launch_bounds__(128)
stage2_kernel(float* __restrict__ out)
{
    const int tid  = threadIdx.x;
    const int w    = tid >> 5;
    const int lane = tid & 31;
    const int g    = lane >> 2;
    const int ti   = lane & 3;

    const size_t row = (size_t)blockIdx.x * 4 + w;
    const uint32_t* __restrict__ Rb = g_rhsh + row * (KF * 12);
    const int sel = (g & 1) ? 0x7632 : 0x5410;

    float acc[4][3][4];
#pragma unroll
    for (int mi = 0; mi < 4; ++mi)
#pragma unroll
        for (int nt = 0; nt < 3; ++nt)
#pragma unroll
            for (int c = 0; c < 4; ++c) acc[mi][nt][c] = 0.0f;

#pragma unroll
    for (int ks = 0; ks < 6; ++ks) {
        const int kp0 = (ks << 3) + ti;      // k-pair rows (kf = 2kp, 2kp+1)
        const int kp1 = kp0 + 4;
        uint32_t af[4][4], bf[3][2];
#pragma unroll
        for (int mi = 0; mi < 4; ++mi) {
            const int o = (mi << 4) + g;
            af[mi][0] = g_thh[(kp0 << 6) + o];
            af[mi][1] = g_thh[(kp0 << 6) + o + 8];
            af[mi][2] = g_thh[(kp1 << 6) + o];
            af[mi][3] = g_thh[(kp1 << 6) + o + 8];
        }
#pragma unroll
        for (int nt = 0; nt < 3; ++nt) {
            const int tp = (nt << 2) + (g >> 1);     // t-pair index, t = 8nt+g
            const uint32_t a0 = Rb[(kp0 << 1) * 12 + tp];
            const uint32_t b0 = Rb[((kp0 << 1) + 1) * 12 + tp];
            const uint32_t a1 = Rb[(kp1 << 1) * 12 + tp];
            const uint32_t b1 = Rb[((kp1 << 1) + 1) * 12 + tp];
            bf[nt][0] = __byte_perm(a0, b0, sel);
            bf[nt][1] = __byte_perm(a1, b1, sel);
        }
#pragma unroll
        for (int mi = 0; mi < 4; ++mi)
#pragma unroll
            for (int nt = 0; nt < 3; ++nt)
                mma_fp16(acc[mi][nt], af[mi], bf[nt]);
    }

    // epilogue: c0:(g,2ti) c1:(g,2ti+1) c2:(g+8,2ti) c3:(g+8,2ti+1)
    float* ob = out + row * (FOUT * TDIM);
#pragma unroll
    for (int mi = 0; mi < 4; ++mi) {
        const int o = (mi << 4) + g;
#pragma unroll
        for (int nt = 0; nt < 3; ++nt) {
            const int t = (nt << 3) + (ti << 1);
            float2 v0 = make_float2(fmaxf(acc[mi][nt][0], 0.0f),
                                    fmaxf(acc[mi][nt][1], 0.0f));
            float2 v1 = make_float2(fmaxf(acc[mi][nt][2], 0.0f),
                                    fmaxf(acc[mi][nt][3], 0.0f));
            *(float2*)(ob + o * TDIM + t) = v0;
            *(float2*)(ob + (o + 8) * TDIM + t) = v1;
        }
    }
}

// ---------------------------------------------------------------------------
extern "C" void kernel_launch(void* const* d_in, const int* in_sizes, int n_in,
                              void* d_out, int out_size)
{
    (void)in_sizes; (void)n_in; (void)out_size;
    const float* x     = (const float*)d_in[0];   // (16,2048,32,24)
    const float* att   = (const float*)d_in[1];   // (16,2048,2048)
    const float* cheb  = (const float*)d_in[2];   // (3,2048,2048)
    const float* Theta = (const float*)d_in[3];   // (3,32,64)
    float* out = (float*)d_out;                   // (16,2048,64,24)

    prepack_kernel<<<BATCH * 1024 * 192 / 256, 256>>>(x);
    theta_prepack_kernel<<<(KF / 2) * FOUT / 256, 256>>>(Theta);
    dim3 g1(JDIM / 256, NNODES / 128, KCHEB * BATCH);   // (3, 16, 48)
    stage1_kernel<<<g1, 256>>>(att, cheb);
    stage2_kernel<<<(BATCH * NNODES) / 4, 128>>>(out);
}